// round 7
// baseline (speedup 1.0000x reference)
#include <cuda_runtime.h>
#include <cuda_bf16.h>
#include <cstdio>

#define D 128
#define ESZ 20
#define MAX_NODES 20000
#define MAX_EDGES 600000
#define CUTOFF 5.0f

// ---------------- scratch (static device bss; no allocations) ----------------
__device__ __align__(16) float g_h1 [MAX_NODES * D];
__device__ __align__(16) float g_so [MAX_NODES * 3 * D];
__device__ __align__(16) float g_s  [MAX_NODES * D];
__device__ __align__(16) float g_v  [MAX_NODES * 3 * D];
__device__ __align__(16) float g_Uv [MAX_NODES * 3 * D];
__device__ __align__(16) float g_Vv [MAX_NODES * 3 * D];
__device__ __align__(16) float g_cat[MAX_NODES * 2 * D];
__device__ __align__(16) float g_ip [MAX_NODES * D];
__device__ __align__(16) float g_h2 [MAX_NODES * D];
__device__ __align__(16) float g_a  [MAX_NODES * 3 * D];

// ---------------- helpers ----------------
__device__ __forceinline__ void red_add_f32(float* addr, float v) {
    asm volatile("red.global.add.f32 [%0], %1;" :: "l"(addr), "f"(v) : "memory");
}
__device__ __forceinline__ float silu_f(float x) {
    return x / (1.0f + __expf(-x));
}

// ---------------- init: copy node states into accumulators ----------------
__global__ void init_copy_kernel(const float* __restrict__ ns, const float* __restrict__ nv, int n) {
    int tid = blockIdx.x * blockDim.x + threadIdx.x;
    int stride = gridDim.x * blockDim.x;
    const float4* ns4 = (const float4*)ns;
    const float4* nv4 = (const float4*)nv;
    float4* s4 = (float4*)g_s;
    float4* v4 = (float4*)g_v;
    int cs = n * (D / 4);
    int cv = n * (3 * D / 4);
    for (int i = tid; i < cs; i += stride) s4[i] = ns4[i];
    for (int i = tid; i < cv; i += stride) v4[i] = nv4[i];
}

// ---------------- generic tiled SGEMM ----------------
template<bool SILU, bool HASBIAS>
__global__ __launch_bounds__(256) void sgemm_kernel(
    const float* __restrict__ A, const float* __restrict__ B,
    const float* __restrict__ bias, float* __restrict__ C,
    int M, int N, int K)
{
    const int BM = 128, BN = 64, BK = 16, TM = 8, TN = 4;
    __shared__ __align__(16) float As[BK][BM + 4];
    __shared__ __align__(16) float Bs[BK][BN];
    int t = threadIdx.x;
    int tx = t & 15;
    int ty = t >> 4;
    int m0 = blockIdx.x * BM;
    int n0 = blockIdx.y * BN;

    float acc[TM][TN];
    #pragma unroll
    for (int i = 0; i < TM; i++)
        #pragma unroll
        for (int j = 0; j < TN; j++) acc[i][j] = 0.0f;

    for (int k0 = 0; k0 < K; k0 += BK) {
        #pragma unroll
        for (int it = 0; it < 2; it++) {
            int l = t + 256 * it;
            int row = l >> 2;
            int kc = (l & 3) * 4;
            float4 v = make_float4(0.f, 0.f, 0.f, 0.f);
            int gr = m0 + row;
            if (gr < M) v = *(const float4*)&A[(size_t)gr * K + k0 + kc];
            As[kc + 0][row] = v.x;
            As[kc + 1][row] = v.y;
            As[kc + 2][row] = v.z;
            As[kc + 3][row] = v.w;
        }
        {
            int row = t >> 4;
            int nc = (t & 15) * 4;
            float4 v = *(const float4*)&B[(size_t)(k0 + row) * N + n0 + nc];
            *(float4*)&Bs[row][nc] = v;
        }
        __syncthreads();
        #pragma unroll
        for (int k = 0; k < BK; k++) {
            float4 a0 = *(float4*)&As[k][ty * TM];
            float4 a1 = *(float4*)&As[k][ty * TM + 4];
            float4 b0 = *(float4*)&Bs[k][tx * TN];
            float ar[TM] = {a0.x, a0.y, a0.z, a0.w, a1.x, a1.y, a1.z, a1.w};
            float br[TN] = {b0.x, b0.y, b0.z, b0.w};
            #pragma unroll
            for (int i = 0; i < TM; i++)
                #pragma unroll
                for (int j = 0; j < TN; j++)
                    acc[i][j] += ar[i] * br[j];
        }
        __syncthreads();
    }

    float4 bv = make_float4(0.f, 0.f, 0.f, 0.f);
    if (HASBIAS) bv = *(const float4*)&bias[n0 + tx * TN];
    #pragma unroll
    for (int i = 0; i < TM; i++) {
        int gr = m0 + ty * TM + i;
        if (gr >= M) continue;
        float4 o;
        o.x = acc[i][0] + bv.x;
        o.y = acc[i][1] + bv.y;
        o.z = acc[i][2] + bv.z;
        o.w = acc[i][3] + bv.w;
        if (SILU) { o.x = silu_f(o.x); o.y = silu_f(o.y); o.z = silu_f(o.z); o.w = silu_f(o.w); }
        *(float4*)&C[(size_t)gr * N + n0 + tx * TN] = o;
    }
}

// ---------------- dual SGEMM: C1 = A@B1, C2 = A@B2 ----------------
__global__ __launch_bounds__(256) void sgemm_dual_kernel(
    const float* __restrict__ A,
    const float* __restrict__ B1, const float* __restrict__ B2,
    float* __restrict__ C1, float* __restrict__ C2,
    int M, int N, int K)
{
    const int BM = 128, BN = 64, BK = 16, TM = 8, TN = 4;
    __shared__ __align__(16) float As[BK][BM + 4];
    __shared__ __align__(16) float Bs1[BK][BN];
    __shared__ __align__(16) float Bs2[BK][BN];
    int t = threadIdx.x;
    int tx = t & 15;
    int ty = t >> 4;
    int m0 = blockIdx.x * BM;
    int n0 = blockIdx.y * BN;

    float acc1[TM][TN], acc2[TM][TN];
    #pragma unroll
    for (int i = 0; i < TM; i++)
        #pragma unroll
        for (int j = 0; j < TN; j++) { acc1[i][j] = 0.0f; acc2[i][j] = 0.0f; }

    for (int k0 = 0; k0 < K; k0 += BK) {
        #pragma unroll
        for (int it = 0; it < 2; it++) {
            int l = t + 256 * it;
            int row = l >> 2;
            int kc = (l & 3) * 4;
            float4 v = make_float4(0.f, 0.f, 0.f, 0.f);
            int gr = m0 + row;
            if (gr < M) v = *(const float4*)&A[(size_t)gr * K + k0 + kc];
            As[kc + 0][row] = v.x;
            As[kc + 1][row] = v.y;
            As[kc + 2][row] = v.z;
            As[kc + 3][row] = v.w;
        }
        {
            int row = t >> 4;
            int nc = (t & 15) * 4;
            *(float4*)&Bs1[row][nc] = *(const float4*)&B1[(size_t)(k0 + row) * N + n0 + nc];
            *(float4*)&Bs2[row][nc] = *(const float4*)&B2[(size_t)(k0 + row) * N + n0 + nc];
        }
        __syncthreads();
        #pragma unroll
        for (int k = 0; k < BK; k++) {
            float4 a0 = *(float4*)&As[k][ty * TM];
            float4 a1 = *(float4*)&As[k][ty * TM + 4];
            float ar[TM] = {a0.x, a0.y, a0.z, a0.w, a1.x, a1.y, a1.z, a1.w};
            float4 b1 = *(float4*)&Bs1[k][tx * TN];
            float4 b2 = *(float4*)&Bs2[k][tx * TN];
            float br1[TN] = {b1.x, b1.y, b1.z, b1.w};
            float br2[TN] = {b2.x, b2.y, b2.z, b2.w};
            #pragma unroll
            for (int i = 0; i < TM; i++)
                #pragma unroll
                for (int j = 0; j < TN; j++) {
                    acc1[i][j] += ar[i] * br1[j];
                    acc2[i][j] += ar[i] * br2[j];
                }
        }
        __syncthreads();
    }

    #pragma unroll
    for (int i = 0; i < TM; i++) {
        int gr = m0 + ty * TM + i;
        if (gr >= M) continue;
        float4 o1, o2;
        o1.x = acc1[i][0]; o1.y = acc1[i][1]; o1.z = acc1[i][2]; o1.w = acc1[i][3];
        o2.x = acc2[i][0]; o2.y = acc2[i][1]; o2.z = acc2[i][2]; o2.w = acc2[i][3];
        *(float4*)&C1[(size_t)gr * N + n0 + tx * TN] = o1;
        *(float4*)&C2[(size_t)gr * N + n0 + tx * TN] = o2;
    }
}

// ---------------- fused edge kernel (v3: 384 threads, 1 col/thread) ----------------
// Thread t: g = t/128 (segment), i = t%128 (channel). Wf column in 20 regs.
// Phase 1: filter+gather; g==2 reds messages_scalar directly; g==0/1 publish
// gn/ge via smem. Phase 2: group g handles vector component c=g.
#define EB 16
__global__ void __launch_bounds__(384, 3) edge_kernel(
    const float* __restrict__ es_g, const float* __restrict__ ev_g,
    const float* __restrict__ norms, const int* __restrict__ eidx,
    const float* __restrict__ Wf, const float* __restrict__ bf,
    const float* __restrict__ nsv, int E)
{
    __shared__ float es_sh[EB][ESZ];
    __shared__ __align__(16) float gn_sh[EB][D];
    __shared__ __align__(16) float ge_sh[EB][D];
    __shared__ int   src_sh[EB], dst_sh[EB];
    __shared__ float ev_sh[EB][3];
    __shared__ float fc_sh[EB];

    int t = threadIdx.x;
    int g = t >> 7;          // 0,1,2
    int i = t & 127;
    int col = (g << 7) + i;  // owned column in [0,384)

    // one Wf column in registers
    float wf[ESZ];
    #pragma unroll
    for (int k = 0; k < ESZ; k++)
        wf[k] = __ldg(&Wf[k * 384 + col]);
    float bfr = __ldg(&bf[col]);

    int nbatch = (E + EB - 1) / EB;
    for (int b = blockIdx.x; b < nbatch; b += gridDim.x) {
        int e0 = b * EB;
        int ecount = min(EB, E - e0);

        // ---- phase 0: stage edge data ----
        if (t < EB * ESZ) {
            int e = t / ESZ;
            es_sh[e][t % ESZ] = (e < ecount) ? __ldg(&es_g[(size_t)e0 * ESZ + t]) : 0.0f;
        }
        if (t >= 352 && t < 352 + EB) {   // a separate warp handles metadata
            int l = t - 352;
            if (l < ecount) {
                int ge_ = e0 + l;
                src_sh[l] = eidx[2 * ge_];
                dst_sh[l] = eidx[2 * ge_ + 1];
                ev_sh[l][0] = ev_g[3 * ge_];
                ev_sh[l][1] = ev_g[3 * ge_ + 1];
                ev_sh[l][2] = ev_g[3 * ge_ + 2];
                float nrm = norms[ge_];
                fc_sh[l] = (nrm < CUTOFF) ? 0.5f * (cospif(nrm / CUTOFF) + 1.0f) : 0.0f;
            } else {
                src_sh[l] = 0; dst_sh[l] = 0;
                ev_sh[l][0] = ev_sh[l][1] = ev_sh[l][2] = 0.f;
                fc_sh[l] = 0.f;
            }
        }
        __syncthreads();

        // ---- phase 1: filter_output for owned column ----
        #pragma unroll 4
        for (int e = 0; e < EB; e++) {
            if (e >= ecount) break;
            int src = src_sh[e];
            float so = __ldg(&g_so[(size_t)src * 384 + col]);
            float acc = bfr;
            #pragma unroll
            for (int k = 0; k < ESZ; k++)
                acc = fmaf(es_sh[e][k], wf[k], acc);
            float fo = acc * fc_sh[e] * so;
            if (g == 0)      gn_sh[e][i] = fo;
            else if (g == 1) ge_sh[e][i] = fo;
            else             red_add_f32(&g_s[(size_t)dst_sh[e] * D + i], fo);
        }
        __syncthreads();

        // ---- phase 2: vector messages, component c = g ----
        #pragma unroll 4
        for (int e = 0; e < EB; e++) {
            if (e >= ecount) break;
            int src = src_sh[e];
            int dst = dst_sh[e];
            float gn = gn_sh[e][i];
            float gee = ge_sh[e][i];
            float evc = ev_sh[e][g];
            float nv = __ldg(&nsv[((size_t)src * 3 + g) * D + i]);
            float mv = fmaf(nv, gn, gee * evc);
            red_add_f32(&g_v[((size_t)dst * 3 + g) * D + i], mv);
        }
        __syncthreads();
    }
}

// ---------------- per-node: Vv_sq, ip, concat ----------------
__global__ void vsq_ip_cat_kernel(int n) {
    int node = blockIdx.x;
    int i = threadIdx.x;  // 128
    float vsq = 0.f, ipv = 0.f;
    #pragma unroll
    for (int c = 0; c < 3; c++) {
        float u = g_Uv[((size_t)node * 3 + c) * D + i];
        float w = g_Vv[((size_t)node * 3 + c) * D + i];
        vsq += w * w;
        ipv += u * w;
    }
    g_cat[(size_t)node * 256 + i]       = g_s[(size_t)node * D + i];
    g_cat[(size_t)node * 256 + D + i]   = vsq;
    g_ip[(size_t)node * D + i]          = ipv;
}

// ---------------- final elementwise ----------------
__global__ void final_kernel(float* __restrict__ out, int n) {
    int node = blockIdx.x;
    int i = threadIdx.x;  // 128
    const float* a = &g_a[(size_t)node * 384];
    float a_ss = a[i];
    float a_sv = a[D + i];
    float a_vv = a[2 * D + i];
    out[(size_t)node * D + i] =
        g_s[(size_t)node * D + i] + a_ss + a_sv * g_ip[(size_t)node * D + i];
    float* vout = out + (size_t)n * D;
    #pragma unroll
    for (int c = 0; c < 3; c++) {
        size_t idx = ((size_t)node * 3 + c) * D + i;
        vout[idx] = g_v[idx] + a_vv * g_Uv[idx];
    }
}

// ---------------- launch ----------------
extern "C" void kernel_launch(void* const* d_in, const int* in_sizes, int n_in,
                              void* d_out, int out_size) {
    const float* ns  = (const float*)d_in[0];
    const float* nv  = (const float*)d_in[1];
    const float* es  = (const float*)d_in[2];
    const float* ev  = (const float*)d_in[3];
    const float* en  = (const float*)d_in[4];
    const int*   ei  = (const int*)  d_in[5];
    const float* Wf  = (const float*)d_in[6];
    const float* bf  = (const float*)d_in[7];
    const float* Wm1 = (const float*)d_in[8];
    const float* bm1 = (const float*)d_in[9];
    const float* Wm2 = (const float*)d_in[10];
    const float* bm2 = (const float*)d_in[11];
    const float* WU  = (const float*)d_in[12];
    const float* WV  = (const float*)d_in[13];
    const float* Wa1 = (const float*)d_in[14];
    const float* ba1 = (const float*)d_in[15];
    const float* Wa2 = (const float*)d_in[16];
    const float* ba2 = (const float*)d_in[17];

    int n = in_sizes[0] / D;
    int E = in_sizes[4];
    float* out = (float*)d_out;

    float *p_h1, *p_so, *p_v, *p_Uv, *p_Vv, *p_cat, *p_h2, *p_a;
    cudaGetSymbolAddress((void**)&p_h1,  g_h1);
    cudaGetSymbolAddress((void**)&p_so,  g_so);
    cudaGetSymbolAddress((void**)&p_v,   g_v);
    cudaGetSymbolAddress((void**)&p_Uv,  g_Uv);
    cudaGetSymbolAddress((void**)&p_Vv,  g_Vv);
    cudaGetSymbolAddress((void**)&p_cat, g_cat);
    cudaGetSymbolAddress((void**)&p_h2,  g_h2);
    cudaGetSymbolAddress((void**)&p_a,   g_a);

    // 1. init accumulators s = ns, v = nv
    init_copy_kernel<<<2048, 256>>>(ns, nv, n);

    // 2. H1 = silu(ns @ Wm1 + bm1)
    {
        dim3 grid((n + 127) / 128, 128 / 64);
        sgemm_kernel<true, true><<<grid, 256>>>(ns, Wm1, bm1, p_h1, n, 128, 128);
    }
    // 3. SO = H1 @ Wm2 + bm2
    {
        dim3 grid((n + 127) / 128, 384 / 64);
        sgemm_kernel<false, true><<<grid, 256>>>(p_h1, Wm2, bm2, p_so, n, 384, 128);
    }
    // 4. fused edge kernel
    {
        int nbatch = (E + EB - 1) / EB;
        int grid = nbatch < 1184 ? nbatch : 1184;
        edge_kernel<<<grid, 384>>>(es, ev, en, ei, Wf, bf, nv, E);
    }
    // 5/6. Uv = v @ WU, Vv = v @ WV
    {
        dim3 grid((3 * n + 127) / 128, 128 / 64);
        sgemm_dual_kernel<<<grid, 256>>>(p_v, WU, WV, p_Uv, p_Vv, 3 * n, 128, 128);
    }
    // 7. Vv_sq, ip, cat
    vsq_ip_cat_kernel<<<n, 128>>>(n);

    // 8. H2 = silu(cat @ Wa1 + ba1)
    {
        dim3 grid((n + 127) / 128, 128 / 64);
        sgemm_kernel<true, true><<<grid, 256>>>(p_cat, Wa1, ba1, p_h2, n, 128, 256);
    }
    // 9. A = H2 @ Wa2 + ba2
    {
        dim3 grid((n + 127) / 128, 384 / 64);
        sgemm_kernel<false, true><<<grid, 256>>>(p_h2, Wa2, ba2, p_a, n, 384, 128);
    }
    // 10. final
    final_kernel<<<n, 128>>>(out, n);
}